// round 9
// baseline (speedup 1.0000x reference)
#include <cuda_runtime.h>

#define H_ 12
#define C_ 768
#define D_ 64
#define B_ 4
#define N_ 2048
#define M_ 8192   // B_*N_

// Scratch (allocation-free: __device__ globals)
__device__ float g_Q[B_ * H_ * N_ * D_];
__device__ float g_K[B_ * H_ * N_ * D_];
__device__ float g_V[B_ * H_ * N_ * D_];
__device__ float g_ctx[M_ * C_];

// ---------------------------------------------------------------------------
// helpers
// ---------------------------------------------------------------------------
__device__ __forceinline__ void mma8(float* c, const unsigned* a, const unsigned* b) {
    asm volatile(
        "mma.sync.aligned.m16n8k8.row.col.f32.tf32.tf32.f32 "
        "{%0,%1,%2,%3},{%4,%5,%6,%7},{%8,%9},{%0,%1,%2,%3};"
        : "+f"(c[0]), "+f"(c[1]), "+f"(c[2]), "+f"(c[3])
        : "r"(a[0]), "r"(a[1]), "r"(a[2]), "r"(a[3]), "r"(b[0]), "r"(b[1]));
}

__device__ __forceinline__ float tf32_rna(float v) {
    unsigned u;
    asm("cvt.rna.tf32.f32 %0, %1;" : "=r"(u) : "f"(v));
    return __uint_as_float(u);
}
__device__ __forceinline__ unsigned tf32_rna_u(float v) {
    unsigned u;
    asm("cvt.rna.tf32.f32 %0, %1;" : "=r"(u) : "f"(v));
    return u;
}

__device__ __forceinline__ void cp16(void* dst, const void* src) {
    unsigned d = (unsigned)__cvta_generic_to_shared(dst);
    asm volatile("cp.async.cg.shared.global [%0], [%1], 16;\n" :: "r"(d), "l"(src));
}
#define CP_COMMIT() asm volatile("cp.async.commit_group;\n" ::: "memory")
#define CP_WAIT1()  asm volatile("cp.async.wait_group 1;\n" ::: "memory")

// ---------------------------------------------------------------------------
// 128x128 tf32 GEMM, 1xTF32 (RNA-rounded operands), cp.async pipelined, BK=16.
// MODE 0: Cout = acc + bias (proj)
// MODE 1: scatter into g_Q (x0.125) / g_K / g_V, tf32-rounded (qkv)
// ---------------------------------------------------------------------------
#define ASTR 20    // As row stride: conflict-free A frag pattern
#define BSTR 136   // Bs row stride: 136 mod 32 == 8 -> conflict-free B frags

template <int MODE>
__global__ __launch_bounds__(256) void mm1x(
    const float* __restrict__ A, const float* __restrict__ Bm,
    const float* __restrict__ bias, float* __restrict__ Cout,
    int K, int N)
{
    __shared__ float As[2][128][ASTR];
    __shared__ float Bs[2][16][BSTR];
    const int tid  = threadIdx.x;
    const int lane = tid & 31, warp = tid >> 5;
    const int g    = lane >> 2, tig = lane & 3;
    const int wm   = (warp >> 2) * 64, wn = (warp & 3) * 32;
    const int m0   = blockIdx.y * 128, n0 = blockIdx.x * 128;

    float acc[16][4];
#pragma unroll
    for (int t = 0; t < 16; t++)
#pragma unroll
        for (int r = 0; r < 4; r++) acc[t][r] = 0.f;

    const int T = K / 16;

    auto prefetch = [&](int s, int buf) {
#pragma unroll
        for (int j = 0; j < 2; j++) {
            int c = tid * 2 + j;
            int ar = c >> 2, ak = c & 3;
            cp16(&As[buf][ar][ak * 4], A + (size_t)(m0 + ar) * K + s * 16 + ak * 4);
            int bk = c >> 5, bn = c & 31;
            cp16(&Bs[buf][bk][bn * 4], Bm + (size_t)(s * 16 + bk) * N + n0 + bn * 4);
        }
    };

    prefetch(0, 0);
    CP_COMMIT();

    for (int t = 0; t < T; t++) {
        int nxt = (t + 1 < T) ? t + 1 : t;
        prefetch(nxt, (t + 1) & 1);
        CP_COMMIT();
        CP_WAIT1();
        __syncthreads();

        int buf = t & 1;
#pragma unroll
        for (int kk = 0; kk < 16; kk += 8) {
            unsigned af[4][4], bf[4][2];
#pragma unroll
            for (int i = 0; i < 4; i++) {
                int m = wm + 16 * i + g;
                af[i][0] = tf32_rna_u(As[buf][m][kk + tig]);
                af[i][1] = tf32_rna_u(As[buf][m + 8][kk + tig]);
                af[i][2] = tf32_rna_u(As[buf][m][kk + tig + 4]);
                af[i][3] = tf32_rna_u(As[buf][m + 8][kk + tig + 4]);
            }
#pragma unroll
            for (int j = 0; j < 4; j++) {
                int n = wn + 8 * j + g;
                bf[j][0] = tf32_rna_u(Bs[buf][kk + tig][n]);
                bf[j][1] = tf32_rna_u(Bs[buf][kk + tig + 4][n]);
            }
#pragma unroll
            for (int i = 0; i < 4; i++)
#pragma unroll
                for (int j = 0; j < 4; j++) mma8(acc[i * 4 + j], af[i], bf[j]);
        }
        __syncthreads();
    }

    if (MODE == 0) {
#pragma unroll
        for (int i = 0; i < 4; i++) {
#pragma unroll
            for (int j = 0; j < 4; j++) {
                int r0 = m0 + wm + 16 * i + g;
                int c0 = n0 + wn + 8 * j + 2 * tig;
                float b0 = bias[c0], b1 = bias[c0 + 1];
                float2 v0 = make_float2(acc[i * 4 + j][0] + b0, acc[i * 4 + j][1] + b1);
                float2 v1 = make_float2(acc[i * 4 + j][2] + b0, acc[i * 4 + j][3] + b1);
                *(float2*)(Cout + (size_t)r0 * N + c0) = v0;
                *(float2*)(Cout + (size_t)(r0 + 8) * N + c0) = v1;
            }
        }
    } else {
#pragma unroll
        for (int i = 0; i < 4; i++) {
#pragma unroll
            for (int j = 0; j < 4; j++) {
                int r0 = m0 + wm + 16 * i + g;
                int c0 = n0 + wn + 8 * j + 2 * tig;
                float b0 = bias[c0], b1 = bias[c0 + 1];
#pragma unroll
                for (int e = 0; e < 4; e++) {
                    int row = r0 + (e >> 1) * 8;
                    int col = c0 + (e & 1);
                    float v = acc[i * 4 + j][e] + ((e & 1) ? b1 : b0);
                    int three = col / C_;
                    int rem = col - three * C_;
                    int hh = rem >> 6, dd = rem & 63;
                    int bb = row >> 11, nn = row & (N_ - 1);
                    size_t idx = (((size_t)(bb * H_ + hh) * N_) + nn) * D_ + dd;
                    if (three == 0)      g_Q[idx] = tf32_rna(v * 0.125f);
                    else if (three == 1) g_K[idx] = tf32_rna(v);
                    else                 g_V[idx] = tf32_rna(v);
                }
            }
        }
    }
}

// ---------------------------------------------------------------------------
// Flash attention, tf32 mma, FIXED-SHIFT softmax (C=20; scores are O(1)-scale
// for this problem, exp(s-C) can neither overflow nor denormal-underflow).
// No per-tile max reduction, no rescaling; l accumulated lane-partially and
// reduced once at the end. Block = 64 queries x (b,h), 128 threads.
// K/Q/P stride 76, V stride 72: all fragment patterns bank-conflict-free.
// ---------------------------------------------------------------------------
#define ST_  76
#define STV_ 72
#define CSHIFT 20.0f

__global__ __launch_bounds__(128) void flash_tf32(
    const float* __restrict__ alibi, const int* __restrict__ mask)
{
    extern __shared__ float sm[];
    float* Kb = sm;                         // [2][64][ST_]
    float* Vb = sm + 2 * 64 * ST_;          // [2][64][STV_]
    float* PQ = Vb + 2 * 64 * STV_;         // [64][ST_]  (Q staging, then P)

    const int tid  = threadIdx.x;
    const int lane = tid & 31, w = tid >> 5;
    const int g    = lane >> 2, tig = lane & 3;
    const int q0   = blockIdx.x * 64, h = blockIdx.y, b = blockIdx.z;
    const int bh   = b * H_ + h;
    float* Ps = PQ + w * 16 * ST_;

    // stage Q [64][64]
    const float* Qg = g_Q + ((size_t)bh * N_ + q0) * D_;
    for (int idx = tid; idx < 64 * 16; idx += 128) {
        int r = idx >> 4, c4 = (idx & 15) << 2;
        *(float4*)&PQ[r * ST_ + c4] = *(const float4*)(Qg + r * D_ + c4);
    }
    __syncthreads();

    // Q frags (resident; warp reads only its own 16 rows, later reused for P)
    unsigned qf[8][4];
    {
        int rlo = w * 16 + g;
#pragma unroll
        for (int kf = 0; kf < 8; kf++) {
            qf[kf][0] = *(const unsigned*)&PQ[rlo * ST_ + 8 * kf + tig];
            qf[kf][1] = *(const unsigned*)&PQ[(rlo + 8) * ST_ + 8 * kf + tig];
            qf[kf][2] = *(const unsigned*)&PQ[rlo * ST_ + 8 * kf + tig + 4];
            qf[kf][3] = *(const unsigned*)&PQ[(rlo + 8) * ST_ + 8 * kf + tig + 4];
        }
    }

    float Oa[8][4];
#pragma unroll
    for (int nt = 0; nt < 8; nt++)
#pragma unroll
        for (int r = 0; r < 4; r++) Oa[nt][r] = 0.f;
    float llo = 0.f, lhi = 0.f;   // lane-partial softmax denominators

    const float* Alo = alibi + ((size_t)bh * N_ + q0 + w * 16 + g) * N_;
    const float* Ahi = Alo + 8 * (size_t)N_;
    const int* Mb = mask + b * N_;

    const float* Kbase = g_K + (size_t)bh * N_ * D_;
    const float* Vbase = g_V + (size_t)bh * N_ * D_;

    auto cp_kv = [&](int t, int buf) {
        const float* Kt = Kbase + (size_t)t * 64 * D_;
        const float* Vt = Vbase + (size_t)t * 64 * D_;
        float* Kd = Kb + buf * 64 * ST_;
        float* Vd = Vb + buf * 64 * STV_;
#pragma unroll
        for (int j = 0; j < 8; j++) {
            int c = tid * 8 + j;
            int row = c >> 4, kc = c & 15;
            cp16(&Kd[row * ST_ + kc * 4], Kt + row * D_ + kc * 4);
            cp16(&Vd[row * STV_ + kc * 4], Vt + row * D_ + kc * 4);
        }
    };

    cp_kv(0, 0);
    CP_COMMIT();

    for (int kt = 0; kt < N_ / 64; kt++) {
        int nxt = (kt + 1 < N_ / 64) ? kt + 1 : kt;
        cp_kv(nxt, (kt + 1) & 1);
        CP_COMMIT();
        CP_WAIT1();
        __syncthreads();

        const float* Ks = Kb + (kt & 1) * 64 * ST_;
        const float* Vs = Vb + (kt & 1) * 64 * STV_;

        // S = Q K^T (tile 16x64 per warp)
        float Sa[8][4];
#pragma unroll
        for (int nt = 0; nt < 8; nt++)
#pragma unroll
            for (int r = 0; r < 4; r++) Sa[nt][r] = 0.f;
#pragma unroll
        for (int nt = 0; nt < 8; nt++) {
            const float* kr = &Ks[(8 * nt + g) * ST_];
#pragma unroll
            for (int kf = 0; kf < 8; kf++) {
                unsigned bfr[2];
                bfr[0] = *(const unsigned*)&kr[8 * kf + tig];
                bfr[1] = *(const unsigned*)&kr[8 * kf + tig + 4];
                mma8(Sa[nt], qf[kf], bfr);
            }
        }

        // P = exp(S + alibi + mask - C); accumulate lane-partial l
        int kbase = kt * 64;
#pragma unroll
        for (int nt = 0; nt < 8; nt++) {
            int c = kbase + 8 * nt + 2 * tig;
            float2 alo = *(const float2*)(Alo + c);
            float2 ahi = *(const float2*)(Ahi + c);
            int2 mk = *(const int2*)(Mb + c);
            float m0v = mk.x ? -1e30f : 0.f;
            float m1v = mk.y ? -1e30f : 0.f;
            float p0 = __expf(Sa[nt][0] + alo.x + m0v - CSHIFT);
            float p1 = __expf(Sa[nt][1] + alo.y + m1v - CSHIFT);
            float p2 = __expf(Sa[nt][2] + ahi.x + m0v - CSHIFT);
            float p3 = __expf(Sa[nt][3] + ahi.y + m1v - CSHIFT);
            Sa[nt][0] = p0; Sa[nt][1] = p1; Sa[nt][2] = p2; Sa[nt][3] = p3;
            llo += p0 + p1;
            lhi += p2 + p3;
        }

        // stage P (warp-private rows) and run PV
#pragma unroll
        for (int nt = 0; nt < 8; nt++) {
            *(float2*)&Ps[g * ST_ + 8 * nt + 2 * tig] = make_float2(Sa[nt][0], Sa[nt][1]);
            *(float2*)&Ps[(g + 8) * ST_ + 8 * nt + 2 * tig] = make_float2(Sa[nt][2], Sa[nt][3]);
        }
        __syncwarp();

        unsigned pf[8][4];
#pragma unroll
        for (int kf = 0; kf < 8; kf++) {
            pf[kf][0] = tf32_rna_u(Ps[g * ST_ + 8 * kf + tig]);
            pf[kf][1] = tf32_rna_u(Ps[(g + 8) * ST_ + 8 * kf + tig]);
            pf[kf][2] = tf32_rna_u(Ps[g * ST_ + 8 * kf + tig + 4]);
            pf[kf][3] = tf32_rna_u(Ps[(g + 8) * ST_ + 8 * kf + tig + 4]);
        }
#pragma unroll
        for (int nt = 0; nt < 8; nt++) {
#pragma unroll
            for (int kf = 0; kf < 8; kf++) {
                unsigned vb[2];
                vb[0] = *(const unsigned*)&Vs[(8 * kf + tig) * STV_ + 8 * nt + g];
                vb[1] = *(const unsigned*)&Vs[(8 * kf + tig + 4) * STV_ + 8 * nt + g];
                mma8(Oa[nt], pf[kf], vb);
            }
        }
        __syncthreads();   // all warps done with this K/V buffer before refill
    }

    // reduce l over the 4 lanes of each row group (single reduction, post-loop)
    llo += __shfl_xor_sync(0xffffffffu, llo, 1);
    llo += __shfl_xor_sync(0xffffffffu, llo, 2);
    lhi += __shfl_xor_sync(0xffffffffu, lhi, 1);
    lhi += __shfl_xor_sync(0xffffffffu, lhi, 2);

    // normalize + write ctx [B*N, C], col = h*64 + d
    float i0 = 1.f / llo, i1 = 1.f / lhi;
    float* Cr  = g_ctx + (size_t)(b * N_ + q0 + w * 16 + g) * C_ + h * D_;
    float* Cr2 = Cr + 8 * (size_t)C_;
#pragma unroll
    for (int nt = 0; nt < 8; nt++) {
        int c = 8 * nt + 2 * tig;
        *(float2*)(Cr + c)  = make_float2(Oa[nt][0] * i0, Oa[nt][1] * i0);
        *(float2*)(Cr2 + c) = make_float2(Oa[nt][2] * i1, Oa[nt][3] * i1);
    }
}

// ---------------------------------------------------------------------------
extern "C" void kernel_launch(void* const* d_in, const int* in_sizes, int n_in,
                              void* d_out, int out_size)
{
    const float* x      = (const float*)d_in[0];
    const int*   mask   = (const int*)d_in[1];
    const float* alibi  = (const float*)d_in[2];
    const float* qkv_w  = (const float*)d_in[3];
    const float* qkv_b  = (const float*)d_in[4];
    const float* proj_w = (const float*)d_in[5];
    const float* proj_b = (const float*)d_in[6];
    float* out = (float*)d_out;

    void* ctx_ptr = nullptr;
    cudaGetSymbolAddress(&ctx_ptr, g_ctx);

    // 1) QKV projection (1xTF32, cp.async pipelined)
    mm1x<1><<<dim3((3 * C_) / 128, M_ / 128), 256>>>(
        x, qkv_w, qkv_b, nullptr, C_, 3 * C_);

    // 2) Flash attention (tf32 mma, fixed-shift softmax)
    const int smem_bytes = (2 * 64 * ST_ + 2 * 64 * STV_ + 64 * ST_) * 4;  // 95232
    cudaFuncSetAttribute(flash_tf32, cudaFuncAttributeMaxDynamicSharedMemorySize,
                         smem_bytes);
    flash_tf32<<<dim3(N_ / 64, H_, B_), 128, smem_bytes>>>(alibi, mask);

    // 3) Output projection (1xTF32, cp.async pipelined)
    mm1x<0><<<dim3(C_ / 128, M_ / 128), 256>>>(
        (const float*)ctx_ptr, proj_w, proj_b, out, C_, C_);
}

// round 11
// speedup vs baseline: 1.2487x; 1.2487x over previous
#include <cuda_runtime.h>

#define H_ 12
#define C_ 768
#define D_ 64
#define B_ 4
#define N_ 2048
#define M_ 8192   // B_*N_

// Scratch (allocation-free: __device__ globals)
__device__ float g_Q[B_ * H_ * N_ * D_];
__device__ float g_K[B_ * H_ * N_ * D_];
__device__ float g_V[B_ * H_ * N_ * D_];
__device__ float g_ctx[M_ * C_];

// ---------------------------------------------------------------------------
// helpers
// ---------------------------------------------------------------------------
__device__ __forceinline__ void mma8(float* c, const unsigned* a, const unsigned* b) {
    asm volatile(
        "mma.sync.aligned.m16n8k8.row.col.f32.tf32.tf32.f32 "
        "{%0,%1,%2,%3},{%4,%5,%6,%7},{%8,%9},{%0,%1,%2,%3};"
        : "+f"(c[0]), "+f"(c[1]), "+f"(c[2]), "+f"(c[3])
        : "r"(a[0]), "r"(a[1]), "r"(a[2]), "r"(a[3]), "r"(b[0]), "r"(b[1]));
}

__device__ __forceinline__ float tf32_rna(float v) {
    unsigned u;
    asm("cvt.rna.tf32.f32 %0, %1;" : "=r"(u) : "f"(v));
    return __uint_as_float(u);
}
__device__ __forceinline__ unsigned tf32_rna_u(float v) {
    unsigned u;
    asm("cvt.rna.tf32.f32 %0, %1;" : "=r"(u) : "f"(v));
    return u;
}

__device__ __forceinline__ void cp16(void* dst, const void* src) {
    unsigned d = (unsigned)__cvta_generic_to_shared(dst);
    asm volatile("cp.async.cg.shared.global [%0], [%1], 16;\n" :: "r"(d), "l"(src));
}
#define CP_COMMIT() asm volatile("cp.async.commit_group;\n" ::: "memory")
#define CP_WAIT1()  asm volatile("cp.async.wait_group 1;\n" ::: "memory")

// ---------------------------------------------------------------------------
// 128x128 tf32 GEMM, 1xTF32 (RNA-rounded operands), cp.async pipelined, BK=16.
// MODE 0: Cout = acc + bias (proj)
// MODE 1: scatter into g_Q (x0.125) / g_K / g_V, tf32-rounded (qkv)
// ---------------------------------------------------------------------------
#define ASTR 20
#define BSTR 136

template <int MODE>
__global__ __launch_bounds__(256) void mm1x(
    const float* __restrict__ A, const float* __restrict__ Bm,
    const float* __restrict__ bias, float* __restrict__ Cout,
    int K, int N)
{
    __shared__ float As[2][128][ASTR];
    __shared__ float Bs[2][16][BSTR];
    const int tid  = threadIdx.x;
    const int lane = tid & 31, warp = tid >> 5;
    const int g    = lane >> 2, tig = lane & 3;
    const int wm   = (warp >> 2) * 64, wn = (warp & 3) * 32;
    const int m0   = blockIdx.y * 128, n0 = blockIdx.x * 128;

    float acc[16][4];
#pragma unroll
    for (int t = 0; t < 16; t++)
#pragma unroll
        for (int r = 0; r < 4; r++) acc[t][r] = 0.f;

    const int T = K / 16;

    auto prefetch = [&](int s, int buf) {
#pragma unroll
        for (int j = 0; j < 2; j++) {
            int c = tid * 2 + j;
            int ar = c >> 2, ak = c & 3;
            cp16(&As[buf][ar][ak * 4], A + (size_t)(m0 + ar) * K + s * 16 + ak * 4);
            int bk = c >> 5, bn = c & 31;
            cp16(&Bs[buf][bk][bn * 4], Bm + (size_t)(s * 16 + bk) * N + n0 + bn * 4);
        }
    };

    prefetch(0, 0);
    CP_COMMIT();

    for (int t = 0; t < T; t++) {
        int nxt = (t + 1 < T) ? t + 1 : t;
        prefetch(nxt, (t + 1) & 1);
        CP_COMMIT();
        CP_WAIT1();
        __syncthreads();

        int buf = t & 1;
#pragma unroll
        for (int kk = 0; kk < 16; kk += 8) {
            unsigned af[4][4], bf[4][2];
#pragma unroll
            for (int i = 0; i < 4; i++) {
                int m = wm + 16 * i + g;
                af[i][0] = tf32_rna_u(As[buf][m][kk + tig]);
                af[i][1] = tf32_rna_u(As[buf][m + 8][kk + tig]);
                af[i][2] = tf32_rna_u(As[buf][m][kk + tig + 4]);
                af[i][3] = tf32_rna_u(As[buf][m + 8][kk + tig + 4]);
            }
#pragma unroll
            for (int j = 0; j < 4; j++) {
                int n = wn + 8 * j + g;
                bf[j][0] = tf32_rna_u(Bs[buf][kk + tig][n]);
                bf[j][1] = tf32_rna_u(Bs[buf][kk + tig + 4][n]);
            }
#pragma unroll
            for (int i = 0; i < 4; i++)
#pragma unroll
                for (int j = 0; j < 4; j++) mma8(acc[i * 4 + j], af[i], bf[j]);
        }
        __syncthreads();
    }

    if (MODE == 0) {
#pragma unroll
        for (int i = 0; i < 4; i++) {
#pragma unroll
            for (int j = 0; j < 4; j++) {
                int r0 = m0 + wm + 16 * i + g;
                int c0 = n0 + wn + 8 * j + 2 * tig;
                float b0 = bias[c0], b1 = bias[c0 + 1];
                float2 v0 = make_float2(acc[i * 4 + j][0] + b0, acc[i * 4 + j][1] + b1);
                float2 v1 = make_float2(acc[i * 4 + j][2] + b0, acc[i * 4 + j][3] + b1);
                *(float2*)(Cout + (size_t)r0 * N + c0) = v0;
                *(float2*)(Cout + (size_t)(r0 + 8) * N + c0) = v1;
            }
        }
    } else {
#pragma unroll
        for (int i = 0; i < 4; i++) {
#pragma unroll
            for (int j = 0; j < 4; j++) {
                int r0 = m0 + wm + 16 * i + g;
                int c0 = n0 + wn + 8 * j + 2 * tig;
                float b0 = bias[c0], b1 = bias[c0 + 1];
#pragma unroll
                for (int e = 0; e < 4; e++) {
                    int row = r0 + (e >> 1) * 8;
                    int col = c0 + (e & 1);
                    float v = acc[i * 4 + j][e] + ((e & 1) ? b1 : b0);
                    int three = col / C_;
                    int rem = col - three * C_;
                    int hh = rem >> 6, dd = rem & 63;
                    int bb = row >> 11, nn = row & (N_ - 1);
                    size_t idx = (((size_t)(bb * H_ + hh) * N_) + nn) * D_ + dd;
                    if (three == 0)      g_Q[idx] = tf32_rna(v * 0.125f);
                    else if (three == 1) g_K[idx] = tf32_rna(v);
                    else                 g_V[idx] = tf32_rna(v);
                }
            }
        }
    }
}

// ---------------------------------------------------------------------------
// Flash attention, tf32 mma, cp.async double-buffered K/V, ONLINE softmax.
// Alibi+mask LDGs are issued into registers BEFORE the QK mma chain so their
// DRAM latency is covered by ~1000 cycles of tensor work (asm volatile
// prevents ptxas from doing this hoist itself).
// Block = 64 queries x (b,h), 128 threads; __launch_bounds__(128,2) pins
// 2 CTAs/SM. K/Q/P stride 76, V stride 72: all LDS patterns conflict-free.
// ---------------------------------------------------------------------------
#define ST_  76
#define STV_ 72

__global__ __launch_bounds__(128, 2) void flash_tf32(
    const float* __restrict__ alibi, const int* __restrict__ mask)
{
    extern __shared__ float sm[];
    float* Kb = sm;                         // [2][64][ST_]
    float* Vb = sm + 2 * 64 * ST_;          // [2][64][STV_]
    float* PQ = Vb + 2 * 64 * STV_;         // [64][ST_]  (Q staging, then P)

    const int tid  = threadIdx.x;
    const int lane = tid & 31, w = tid >> 5;
    const int g    = lane >> 2, tig = lane & 3;
    const int q0   = blockIdx.x * 64, h = blockIdx.y, b = blockIdx.z;
    const int bh   = b * H_ + h;
    float* Ps = PQ + w * 16 * ST_;

    // stage Q [64][64]
    const float* Qg = g_Q + ((size_t)bh * N_ + q0) * D_;
    for (int idx = tid; idx < 64 * 16; idx += 128) {
        int r = idx >> 4, c4 = (idx & 15) << 2;
        *(float4*)&PQ[r * ST_ + c4] = *(const float4*)(Qg + r * D_ + c4);
    }
    __syncthreads();

    // Q frags (resident; warp reads only its own 16 rows, later reused for P)
    unsigned qf[8][4];
    {
        int rlo = w * 16 + g;
#pragma unroll
        for (int kf = 0; kf < 8; kf++) {
            qf[kf][0] = *(const unsigned*)&PQ[rlo * ST_ + 8 * kf + tig];
            qf[kf][1] = *(const unsigned*)&PQ[(rlo + 8) * ST_ + 8 * kf + tig];
            qf[kf][2] = *(const unsigned*)&PQ[rlo * ST_ + 8 * kf + tig + 4];
            qf[kf][3] = *(const unsigned*)&PQ[(rlo + 8) * ST_ + 8 * kf + tig + 4];
        }
    }

    float Oa[8][4];
#pragma unroll
    for (int nt = 0; nt < 8; nt++)
#pragma unroll
        for (int r = 0; r < 4; r++) Oa[nt][r] = 0.f;
    float mlo = -1e30f, mhi = -1e30f, llo = 0.f, lhi = 0.f;

    const float* Alo = alibi + ((size_t)bh * N_ + q0 + w * 16 + g) * N_;
    const float* Ahi = Alo + 8 * (size_t)N_;
    const int* Mb = mask + b * N_;

    const float* Kbase = g_K + (size_t)bh * N_ * D_;
    const float* Vbase = g_V + (size_t)bh * N_ * D_;

    auto cp_kv = [&](int t, int buf) {
        const float* Kt = Kbase + (size_t)t * 64 * D_;
        const float* Vt = Vbase + (size_t)t * 64 * D_;
        float* Kd = Kb + buf * 64 * ST_;
        float* Vd = Vb + buf * 64 * STV_;
#pragma unroll
        for (int j = 0; j < 8; j++) {
            int c = tid * 8 + j;
            int row = c >> 4, kc = c & 15;
            cp16(&Kd[row * ST_ + kc * 4], Kt + row * D_ + kc * 4);
            cp16(&Vd[row * STV_ + kc * 4], Vt + row * D_ + kc * 4);
        }
    };

    cp_kv(0, 0);
    CP_COMMIT();

    for (int kt = 0; kt < N_ / 64; kt++) {
        int nxt = (kt + 1 < N_ / 64) ? kt + 1 : kt;
        cp_kv(nxt, (kt + 1) & 1);
        CP_COMMIT();
        CP_WAIT1();
        __syncthreads();

        const float* Ks = Kb + (kt & 1) * 64 * ST_;
        const float* Vs = Vb + (kt & 1) * 64 * STV_;

        // ---- issue alibi + mask loads FIRST (latency covered by QK mma) ----
        int kbase = kt * 64;
        float2 alo_r[8], ahi_r[8];
        int2   mk_r[8];
#pragma unroll
        for (int nt = 0; nt < 8; nt++) {
            int c = kbase + 8 * nt + 2 * tig;
            alo_r[nt] = *(const float2*)(Alo + c);
            ahi_r[nt] = *(const float2*)(Ahi + c);
            mk_r[nt]  = *(const int2*)(Mb + c);
        }

        // S = Q K^T (tile 16x64 per warp)
        float Sa[8][4];
#pragma unroll
        for (int nt = 0; nt < 8; nt++)
#pragma unroll
            for (int r = 0; r < 4; r++) Sa[nt][r] = 0.f;
#pragma unroll
        for (int nt = 0; nt < 8; nt++) {
            const float* kr = &Ks[(8 * nt + g) * ST_];
#pragma unroll
            for (int kf = 0; kf < 8; kf++) {
                unsigned bfr[2];
                bfr[0] = *(const unsigned*)&kr[8 * kf + tig];
                bfr[1] = *(const unsigned*)&kr[8 * kf + tig + 4];
                mma8(Sa[nt], qf[kf], bfr);
            }
        }

        // + alibi + mask (already in registers)
#pragma unroll
        for (int nt = 0; nt < 8; nt++) {
            float m0v = mk_r[nt].x ? -1e30f : 0.f;
            float m1v = mk_r[nt].y ? -1e30f : 0.f;
            Sa[nt][0] += alo_r[nt].x + m0v;
            Sa[nt][1] += alo_r[nt].y + m1v;
            Sa[nt][2] += ahi_r[nt].x + m0v;
            Sa[nt][3] += ahi_r[nt].y + m1v;
        }

        // online softmax
        float mx0 = -1e38f, mx1 = -1e38f;
#pragma unroll
        for (int nt = 0; nt < 8; nt++) {
            mx0 = fmaxf(mx0, fmaxf(Sa[nt][0], Sa[nt][1]));
            mx1 = fmaxf(mx1, fmaxf(Sa[nt][2], Sa[nt][3]));
        }
        mx0 = fmaxf(mx0, __shfl_xor_sync(0xffffffffu, mx0, 1));
        mx0 = fmaxf(mx0, __shfl_xor_sync(0xffffffffu, mx0, 2));
        mx1 = fmaxf(mx1, __shfl_xor_sync(0xffffffffu, mx1, 1));
        mx1 = fmaxf(mx1, __shfl_xor_sync(0xffffffffu, mx1, 2));
        float mn0 = fmaxf(mlo, mx0), mn1 = fmaxf(mhi, mx1);
        float cr0 = __expf(mlo - mn0), cr1 = __expf(mhi - mn1);
        mlo = mn0; mhi = mn1;
        float rs0 = 0.f, rs1 = 0.f;
#pragma unroll
        for (int nt = 0; nt < 8; nt++) {
            float p0 = __expf(Sa[nt][0] - mn0);
            float p1 = __expf(Sa[nt][1] - mn0);
            float p2 = __expf(Sa[nt][2] - mn1);
            float p3 = __expf(Sa[nt][3] - mn1);
            Sa[nt][0] = p0; Sa[nt][1] = p1; Sa[nt][2] = p2; Sa[nt][3] = p3;
            rs0 += p0 + p1;
            rs1 += p2 + p3;
        }
        rs0 += __shfl_xor_sync(0xffffffffu, rs0, 1);
        rs0 += __shfl_xor_sync(0xffffffffu, rs0, 2);
        rs1 += __shfl_xor_sync(0xffffffffu, rs1, 1);
        rs1 += __shfl_xor_sync(0xffffffffu, rs1, 2);
        llo = llo * cr0 + rs0;
        lhi = lhi * cr1 + rs1;
#pragma unroll
        for (int nt = 0; nt < 8; nt++) {
            Oa[nt][0] *= cr0; Oa[nt][1] *= cr0;
            Oa[nt][2] *= cr1; Oa[nt][3] *= cr1;
        }

        // stage P (warp-private rows) and run PV
#pragma unroll
        for (int nt = 0; nt < 8; nt++) {
            *(float2*)&Ps[g * ST_ + 8 * nt + 2 * tig] = make_float2(Sa[nt][0], Sa[nt][1]);
            *(float2*)&Ps[(g + 8) * ST_ + 8 * nt + 2 * tig] = make_float2(Sa[nt][2], Sa[nt][3]);
        }
        __syncwarp();

        unsigned pf[8][4];
#pragma unroll
        for (int kf = 0; kf < 8; kf++) {
            pf[kf][0] = tf32_rna_u(Ps[g * ST_ + 8 * kf + tig]);
            pf[kf][1] = tf32_rna_u(Ps[(g + 8) * ST_ + 8 * kf + tig]);
            pf[kf][2] = tf32_rna_u(Ps[g * ST_ + 8 * kf + tig + 4]);
            pf[kf][3] = tf32_rna_u(Ps[(g + 8) * ST_ + 8 * kf + tig + 4]);
        }
#pragma unroll
        for (int nt = 0; nt < 8; nt++) {
#pragma unroll
            for (int kf = 0; kf < 8; kf++) {
                unsigned vb[2];
                vb[0] = *(const unsigned*)&Vs[(8 * kf + tig) * STV_ + 8 * nt + g];
                vb[1] = *(const unsigned*)&Vs[(8 * kf + tig + 4) * STV_ + 8 * nt + g];
                mma8(Oa[nt], pf[kf], vb);
            }
        }
        __syncthreads();   // all warps done with this K/V buffer before refill
    }

    // normalize + write ctx [B*N, C], col = h*64 + d
    float i0 = 1.f / llo, i1 = 1.f / lhi;
    float* Cr  = g_ctx + (size_t)(b * N_ + q0 + w * 16 + g) * C_ + h * D_;
    float* Cr2 = Cr + 8 * (size_t)C_;
#pragma unroll
    for (int nt = 0; nt < 8; nt++) {
        int c = 8 * nt + 2 * tig;
        *(float2*)(Cr + c)  = make_float2(Oa[nt][0] * i0, Oa[nt][1] * i0);
        *(float2*)(Cr2 + c) = make_float2(Oa[nt][2] * i1, Oa[nt][3] * i1);
    }
}

// ---------------------------------------------------------------------------
extern "C" void kernel_launch(void* const* d_in, const int* in_sizes, int n_in,
                              void* d_out, int out_size)
{
    const float* x      = (const float*)d_in[0];
    const int*   mask   = (const int*)d_in[1];
    const float* alibi  = (const float*)d_in[2];
    const float* qkv_w  = (const float*)d_in[3];
    const float* qkv_b  = (const float*)d_in[4];
    const float* proj_w = (const float*)d_in[5];
    const float* proj_b = (const float*)d_in[6];
    float* out = (float*)d_out;

    void* ctx_ptr = nullptr;
    cudaGetSymbolAddress(&ctx_ptr, g_ctx);

    // 1) QKV projection (1xTF32, cp.async pipelined)
    mm1x<1><<<dim3((3 * C_) / 128, M_ / 128), 256>>>(
        x, qkv_w, qkv_b, nullptr, C_, 3 * C_);

    // 2) Flash attention (tf32 mma, online softmax, alibi reg-prefetch)
    const int smem_bytes = (2 * 64 * ST_ + 2 * 64 * STV_ + 64 * ST_) * 4;  // 95232
    cudaFuncSetAttribute(flash_tf32, cudaFuncAttributeMaxDynamicSharedMemorySize,
                         smem_bytes);
    flash_tf32<<<dim3(N_ / 64, H_, B_), 128, smem_bytes>>>(alibi, mask);

    // 3) Output projection (1xTF32, cp.async pipelined)
    mm1x<0><<<dim3(C_ / 128, M_ / 128), 256>>>(
        (const float*)ctx_ptr, proj_w, proj_b, out, C_, C_);
}

// round 12
// speedup vs baseline: 1.2872x; 1.0308x over previous
#include <cuda_runtime.h>

#define H_ 12
#define C_ 768
#define D_ 64
#define B_ 4
#define N_ 2048
#define M_ 8192   // B_*N_

// Scratch (allocation-free: __device__ globals)
__device__ float g_Q[B_ * H_ * N_ * D_];
__device__ float g_K[B_ * H_ * N_ * D_];
__device__ float g_V[B_ * H_ * N_ * D_];
__device__ float g_ctx[M_ * C_];

// ---------------------------------------------------------------------------
// helpers
// ---------------------------------------------------------------------------
__device__ __forceinline__ void mma8(float* c, const unsigned* a, const unsigned* b) {
    asm volatile(
        "mma.sync.aligned.m16n8k8.row.col.f32.tf32.tf32.f32 "
        "{%0,%1,%2,%3},{%4,%5,%6,%7},{%8,%9},{%0,%1,%2,%3};"
        : "+f"(c[0]), "+f"(c[1]), "+f"(c[2]), "+f"(c[3])
        : "r"(a[0]), "r"(a[1]), "r"(a[2]), "r"(a[3]), "r"(b[0]), "r"(b[1]));
}

__device__ __forceinline__ float tf32_rna(float v) {
    unsigned u;
    asm("cvt.rna.tf32.f32 %0, %1;" : "=r"(u) : "f"(v));
    return __uint_as_float(u);
}
__device__ __forceinline__ unsigned tf32_rna_u(float v) {
    unsigned u;
    asm("cvt.rna.tf32.f32 %0, %1;" : "=r"(u) : "f"(v));
    return u;
}

__device__ __forceinline__ void cp16(void* dst, const void* src) {
    unsigned d = (unsigned)__cvta_generic_to_shared(dst);
    asm volatile("cp.async.cg.shared.global [%0], [%1], 16;\n" :: "r"(d), "l"(src));
}
#define CP_COMMIT() asm volatile("cp.async.commit_group;\n" ::: "memory")
#define CP_WAIT0()  asm volatile("cp.async.wait_group 0;\n" ::: "memory")
#define CP_WAIT1()  asm volatile("cp.async.wait_group 1;\n" ::: "memory")

// ---------------------------------------------------------------------------
// 128x128 tf32 GEMM, 1xTF32 (RNA-rounded operands), cp.async pipelined, BK=16.
// MODE 0: Cout = acc + bias (proj)
// MODE 1: scatter into g_Q (x0.125) / g_K / g_V, tf32-rounded (qkv)
// ---------------------------------------------------------------------------
#define ASTR 20
#define BSTR 136

template <int MODE>
__global__ __launch_bounds__(256) void mm1x(
    const float* __restrict__ A, const float* __restrict__ Bm,
    const float* __restrict__ bias, float* __restrict__ Cout,
    int K, int N)
{
    __shared__ float As[2][128][ASTR];
    __shared__ float Bs[2][16][BSTR];
    const int tid  = threadIdx.x;
    const int lane = tid & 31, warp = tid >> 5;
    const int g    = lane >> 2, tig = lane & 3;
    const int wm   = (warp >> 2) * 64, wn = (warp & 3) * 32;
    const int m0   = blockIdx.y * 128, n0 = blockIdx.x * 128;

    float acc[16][4];
#pragma unroll
    for (int t = 0; t < 16; t++)
#pragma unroll
        for (int r = 0; r < 4; r++) acc[t][r] = 0.f;

    const int T = K / 16;

    auto prefetch = [&](int s, int buf) {
#pragma unroll
        for (int j = 0; j < 2; j++) {
            int c = tid * 2 + j;
            int ar = c >> 2, ak = c & 3;
            cp16(&As[buf][ar][ak * 4], A + (size_t)(m0 + ar) * K + s * 16 + ak * 4);
            int bk = c >> 5, bn = c & 31;
            cp16(&Bs[buf][bk][bn * 4], Bm + (size_t)(s * 16 + bk) * N + n0 + bn * 4);
        }
    };

    prefetch(0, 0);
    CP_COMMIT();

    for (int t = 0; t < T; t++) {
        int nxt = (t + 1 < T) ? t + 1 : t;
        prefetch(nxt, (t + 1) & 1);
        CP_COMMIT();
        CP_WAIT1();
        __syncthreads();

        int buf = t & 1;
#pragma unroll
        for (int kk = 0; kk < 16; kk += 8) {
            unsigned af[4][4], bf[4][2];
#pragma unroll
            for (int i = 0; i < 4; i++) {
                int m = wm + 16 * i + g;
                af[i][0] = tf32_rna_u(As[buf][m][kk + tig]);
                af[i][1] = tf32_rna_u(As[buf][m + 8][kk + tig]);
                af[i][2] = tf32_rna_u(As[buf][m][kk + tig + 4]);
                af[i][3] = tf32_rna_u(As[buf][m + 8][kk + tig + 4]);
            }
#pragma unroll
            for (int j = 0; j < 4; j++) {
                int n = wn + 8 * j + g;
                bf[j][0] = tf32_rna_u(Bs[buf][kk + tig][n]);
                bf[j][1] = tf32_rna_u(Bs[buf][kk + tig + 4][n]);
            }
#pragma unroll
            for (int i = 0; i < 4; i++)
#pragma unroll
                for (int j = 0; j < 4; j++) mma8(acc[i * 4 + j], af[i], bf[j]);
        }
        __syncthreads();
    }

    if (MODE == 0) {
#pragma unroll
        for (int i = 0; i < 4; i++) {
#pragma unroll
            for (int j = 0; j < 4; j++) {
                int r0 = m0 + wm + 16 * i + g;
                int c0 = n0 + wn + 8 * j + 2 * tig;
                float b0 = bias[c0], b1 = bias[c0 + 1];
                float2 v0 = make_float2(acc[i * 4 + j][0] + b0, acc[i * 4 + j][1] + b1);
                float2 v1 = make_float2(acc[i * 4 + j][2] + b0, acc[i * 4 + j][3] + b1);
                *(float2*)(Cout + (size_t)r0 * N + c0) = v0;
                *(float2*)(Cout + (size_t)(r0 + 8) * N + c0) = v1;
            }
        }
    } else {
#pragma unroll
        for (int i = 0; i < 4; i++) {
#pragma unroll
            for (int j = 0; j < 4; j++) {
                int r0 = m0 + wm + 16 * i + g;
                int c0 = n0 + wn + 8 * j + 2 * tig;
                float b0 = bias[c0], b1 = bias[c0 + 1];
#pragma unroll
                for (int e = 0; e < 4; e++) {
                    int row = r0 + (e >> 1) * 8;
                    int col = c0 + (e & 1);
                    float v = acc[i * 4 + j][e] + ((e & 1) ? b1 : b0);
                    int three = col / C_;
                    int rem = col - three * C_;
                    int hh = rem >> 6, dd = rem & 63;
                    int bb = row >> 11, nn = row & (N_ - 1);
                    size_t idx = (((size_t)(bb * H_ + hh) * N_) + nn) * D_ + dd;
                    if (three == 0)      g_Q[idx] = tf32_rna(v * 0.125f);
                    else if (three == 1) g_K[idx] = tf32_rna(v);
                    else                 g_V[idx] = tf32_rna(v);
                }
            }
        }
    }
}

// ---------------------------------------------------------------------------
// Flash attention, tf32 mma, SINGLE-buffered cp.async K/V (smem 57,344 B ->
// 3 CTAs/SM = 12 warps; occupancy is the binding constraint per R3-R10 data).
// Block = 64 queries x (b,h), 128 threads; online softmax.
// K/Q/P stride 76 (==12 mod 32), V stride 72 (==8 mod 32): all fragment LDS
// patterns bank-conflict-free.
// ---------------------------------------------------------------------------
#define ST_  76
#define STV_ 72

__global__ __launch_bounds__(128, 3) void flash_tf32(
    const float* __restrict__ alibi, const int* __restrict__ mask)
{
    extern __shared__ float sm[];
    float* Ks = sm;                         // [64][ST_]
    float* Vs = sm + 64 * ST_;              // [64][STV_]
    float* PQ = Vs + 64 * STV_;             // [64][ST_]  (Q staging, then P)

    const int tid  = threadIdx.x;
    const int lane = tid & 31, w = tid >> 5;
    const int g    = lane >> 2, tig = lane & 3;
    const int q0   = blockIdx.x * 64, h = blockIdx.y, b = blockIdx.z;
    const int bh   = b * H_ + h;
    float* Ps = PQ + w * 16 * ST_;

    // stage Q [64][64]
    const float* Qg = g_Q + ((size_t)bh * N_ + q0) * D_;
    for (int idx = tid; idx < 64 * 16; idx += 128) {
        int r = idx >> 4, c4 = (idx & 15) << 2;
        *(float4*)&PQ[r * ST_ + c4] = *(const float4*)(Qg + r * D_ + c4);
    }
    __syncthreads();

    // Q frags (resident; warp reads only its own 16 rows, later reused for P)
    unsigned qf[8][4];
    {
        int rlo = w * 16 + g;
#pragma unroll
        for (int kf = 0; kf < 8; kf++) {
            qf[kf][0] = *(const unsigned*)&PQ[rlo * ST_ + 8 * kf + tig];
            qf[kf][1] = *(const unsigned*)&PQ[(rlo + 8) * ST_ + 8 * kf + tig];
            qf[kf][2] = *(const unsigned*)&PQ[rlo * ST_ + 8 * kf + tig + 4];
            qf[kf][3] = *(const unsigned*)&PQ[(rlo + 8) * ST_ + 8 * kf + tig + 4];
        }
    }

    float Oa[8][4];
#pragma unroll
    for (int nt = 0; nt < 8; nt++)
#pragma unroll
        for (int r = 0; r < 4; r++) Oa[nt][r] = 0.f;
    float mlo = -1e30f, mhi = -1e30f, llo = 0.f, lhi = 0.f;

    const float* Alo = alibi + ((size_t)bh * N_ + q0 + w * 16 + g) * N_;
    const float* Ahi = Alo + 8 * (size_t)N_;
    const int* Mb = mask + b * N_;

    const float* Kbase = g_K + (size_t)bh * N_ * D_;
    const float* Vbase = g_V + (size_t)bh * N_ * D_;

    for (int kt = 0; kt < N_ / 64; kt++) {
        __syncthreads();   // prior tile's reads of Ks/Vs complete (and Q init)

        // fill K/V tile (single buffer, cp.async)
        {
            const float* Kt = Kbase + (size_t)kt * 64 * D_;
            const float* Vt = Vbase + (size_t)kt * 64 * D_;
#pragma unroll
            for (int j = 0; j < 8; j++) {
                int c = tid * 8 + j;
                int row = c >> 4, kc = c & 15;
                cp16(&Ks[row * ST_ + kc * 4], Kt + row * D_ + kc * 4);
                cp16(&Vs[row * STV_ + kc * 4], Vt + row * D_ + kc * 4);
            }
        }
        CP_COMMIT();
        CP_WAIT0();
        __syncthreads();

        // S = Q K^T (tile 16x64 per warp)
        float Sa[8][4];
#pragma unroll
        for (int nt = 0; nt < 8; nt++)
#pragma unroll
            for (int r = 0; r < 4; r++) Sa[nt][r] = 0.f;
#pragma unroll
        for (int nt = 0; nt < 8; nt++) {
            const float* kr = &Ks[(8 * nt + g) * ST_];
#pragma unroll
            for (int kf = 0; kf < 8; kf++) {
                unsigned bfr[2];
                bfr[0] = *(const unsigned*)&kr[8 * kf + tig];
                bfr[1] = *(const unsigned*)&kr[8 * kf + tig + 4];
                mma8(Sa[nt], qf[kf], bfr);
            }
        }

        // + alibi + mask (via L2/DRAM)
        int kbase = kt * 64;
#pragma unroll
        for (int nt = 0; nt < 8; nt++) {
            int c = kbase + 8 * nt + 2 * tig;
            float2 alo = *(const float2*)(Alo + c);
            float2 ahi = *(const float2*)(Ahi + c);
            int2 mk = *(const int2*)(Mb + c);
            float m0v = mk.x ? -1e30f : 0.f;
            float m1v = mk.y ? -1e30f : 0.f;
            Sa[nt][0] += alo.x + m0v;
            Sa[nt][1] += alo.y + m1v;
            Sa[nt][2] += ahi.x + m0v;
            Sa[nt][3] += ahi.y + m1v;
        }

        // online softmax
        float mx0 = -1e38f, mx1 = -1e38f;
#pragma unroll
        for (int nt = 0; nt < 8; nt++) {
            mx0 = fmaxf(mx0, fmaxf(Sa[nt][0], Sa[nt][1]));
            mx1 = fmaxf(mx1, fmaxf(Sa[nt][2], Sa[nt][3]));
        }
        mx0 = fmaxf(mx0, __shfl_xor_sync(0xffffffffu, mx0, 1));
        mx0 = fmaxf(mx0, __shfl_xor_sync(0xffffffffu, mx0, 2));
        mx1 = fmaxf(mx1, __shfl_xor_sync(0xffffffffu, mx1, 1));
        mx1 = fmaxf(mx1, __shfl_xor_sync(0xffffffffu, mx1, 2));
        float mn0 = fmaxf(mlo, mx0), mn1 = fmaxf(mhi, mx1);
        float cr0 = __expf(mlo - mn0), cr1 = __expf(mhi - mn1);
        mlo = mn0; mhi = mn1;
        float rs0 = 0.f, rs1 = 0.f;
#pragma unroll
        for (int nt = 0; nt < 8; nt++) {
            float p0 = __expf(Sa[nt][0] - mn0);
            float p1 = __expf(Sa[nt][1] - mn0);
            float p2 = __expf(Sa[nt][2] - mn1);
            float p3 = __expf(Sa[nt][3] - mn1);
            Sa[nt][0] = p0; Sa[nt][1] = p1; Sa[nt][2] = p2; Sa[nt][3] = p3;
            rs0 += p0 + p1;
            rs1 += p2 + p3;
        }
        rs0 += __shfl_xor_sync(0xffffffffu, rs0, 1);
        rs0 += __shfl_xor_sync(0xffffffffu, rs0, 2);
        rs1 += __shfl_xor_sync(0xffffffffu, rs1, 1);
        rs1 += __shfl_xor_sync(0xffffffffu, rs1, 2);
        llo = llo * cr0 + rs0;
        lhi = lhi * cr1 + rs1;
#pragma unroll
        for (int nt = 0; nt < 8; nt++) {
            Oa[nt][0] *= cr0; Oa[nt][1] *= cr0;
            Oa[nt][2] *= cr1; Oa[nt][3] *= cr1;
        }

        // stage P (warp-private rows) and run PV
#pragma unroll
        for (int nt = 0; nt < 8; nt++) {
            *(float2*)&Ps[g * ST_ + 8 * nt + 2 * tig] = make_float2(Sa[nt][0], Sa[nt][1]);
            *(float2*)&Ps[(g + 8) * ST_ + 8 * nt + 2 * tig] = make_float2(Sa[nt][2], Sa[nt][3]);
        }
        __syncwarp();

        unsigned pf[8][4];
#pragma unroll
        for (int kf = 0; kf < 8; kf++) {
            pf[kf][0] = tf32_rna_u(Ps[g * ST_ + 8 * kf + tig]);
            pf[kf][1] = tf32_rna_u(Ps[(g + 8) * ST_ + 8 * kf + tig]);
            pf[kf][2] = tf32_rna_u(Ps[g * ST_ + 8 * kf + tig + 4]);
            pf[kf][3] = tf32_rna_u(Ps[(g + 8) * ST_ + 8 * kf + tig + 4]);
        }
#pragma unroll
        for (int nt = 0; nt < 8; nt++) {
#pragma unroll
            for (int kf = 0; kf < 8; kf++) {
                unsigned vb[2];
                vb[0] = *(const unsigned*)&Vs[(8 * kf + tig) * STV_ + 8 * nt + g];
                vb[1] = *(const unsigned*)&Vs[(8 * kf + tig + 4) * STV_ + 8 * nt + g];
                mma8(Oa[nt], pf[kf], vb);
            }
        }
    }

    // normalize + write ctx [B*N, C], col = h*64 + d
    float i0 = 1.f / llo, i1 = 1.f / lhi;
    float* Cr  = g_ctx + (size_t)(b * N_ + q0 + w * 16 + g) * C_ + h * D_;
    float* Cr2 = Cr + 8 * (size_t)C_;
#pragma unroll
    for (int nt = 0; nt < 8; nt++) {
        int c = 8 * nt + 2 * tig;
        *(float2*)(Cr + c)  = make_float2(Oa[nt][0] * i0, Oa[nt][1] * i0);
        *(float2*)(Cr2 + c) = make_float2(Oa[nt][2] * i1, Oa[nt][3] * i1);
    }
}

// ---------------------------------------------------------------------------
extern "C" void kernel_launch(void* const* d_in, const int* in_sizes, int n_in,
                              void* d_out, int out_size)
{
    const float* x      = (const float*)d_in[0];
    const int*   mask   = (const int*)d_in[1];
    const float* alibi  = (const float*)d_in[2];
    const float* qkv_w  = (const float*)d_in[3];
    const float* qkv_b  = (const float*)d_in[4];
    const float* proj_w = (const float*)d_in[5];
    const float* proj_b = (const float*)d_in[6];
    float* out = (float*)d_out;

    void* ctx_ptr = nullptr;
    cudaGetSymbolAddress(&ctx_ptr, g_ctx);

    // 1) QKV projection (1xTF32, cp.async pipelined)
    mm1x<1><<<dim3((3 * C_) / 128, M_ / 128), 256>>>(
        x, qkv_w, qkv_b, nullptr, C_, 3 * C_);

    // 2) Flash attention (tf32 mma, single-buffer, 3 CTAs/SM)
    const int smem_bytes = (64 * ST_ + 64 * STV_ + 64 * ST_) * 4;   // 57344
    cudaFuncSetAttribute(flash_tf32, cudaFuncAttributeMaxDynamicSharedMemorySize,
                         smem_bytes);
    flash_tf32<<<dim3(N_ / 64, H_, B_), 128, smem_bytes>>>(alibi, mask);

    // 3) Output projection (1xTF32, cp.async pipelined)
    mm1x<0><<<dim3(C_ / 128, M_ / 128), 256>>>(
        (const float*)ctx_ptr, proj_w, proj_b, out, C_, C_);
}

// round 13
// speedup vs baseline: 1.3294x; 1.0328x over previous
#include <cuda_runtime.h>

#define H_ 12
#define C_ 768
#define D_ 64
#define B_ 4
#define N_ 2048
#define M_ 8192   // B_*N_

// Scratch (allocation-free: __device__ globals)
__device__ float g_Q[B_ * H_ * N_ * D_];
__device__ float g_K[B_ * H_ * N_ * D_];
__device__ float g_V[B_ * H_ * N_ * D_];   // stored TRANSPOSED: [b,h,d,n]
__device__ float g_ctx[M_ * C_];

// ---------------------------------------------------------------------------
// helpers
// ---------------------------------------------------------------------------
__device__ __forceinline__ void mma8(float* c, const unsigned* a, const unsigned* b) {
    asm volatile(
        "mma.sync.aligned.m16n8k8.row.col.f32.tf32.tf32.f32 "
        "{%0,%1,%2,%3},{%4,%5,%6,%7},{%8,%9},{%0,%1,%2,%3};"
        : "+f"(c[0]), "+f"(c[1]), "+f"(c[2]), "+f"(c[3])
        : "r"(a[0]), "r"(a[1]), "r"(a[2]), "r"(a[3]), "r"(b[0]), "r"(b[1]));
}

__device__ __forceinline__ float tf32_rna(float v) {
    unsigned u;
    asm("cvt.rna.tf32.f32 %0, %1;" : "=r"(u) : "f"(v));
    return __uint_as_float(u);
}
__device__ __forceinline__ unsigned tf32_rna_u(float v) {
    unsigned u;
    asm("cvt.rna.tf32.f32 %0, %1;" : "=r"(u) : "f"(v));
    return u;
}

__device__ __forceinline__ void cp16(void* dst, const void* src) {
    unsigned d = (unsigned)__cvta_generic_to_shared(dst);
    asm volatile("cp.async.cg.shared.global [%0], [%1], 16;\n" :: "r"(d), "l"(src));
}
#define CP_COMMIT() asm volatile("cp.async.commit_group;\n" ::: "memory")
#define CP_WAIT0()  asm volatile("cp.async.wait_group 0;\n" ::: "memory")
#define CP_WAIT1()  asm volatile("cp.async.wait_group 1;\n" ::: "memory")

// ldmatrix x4: four 8x8 b16 tiles = two 8x8 tf32 tiles (lo/hi 4-col halves)
__device__ __forceinline__ void ldsm4(unsigned* r, const void* p) {
    unsigned a = (unsigned)__cvta_generic_to_shared(p);
    asm volatile("ldmatrix.sync.aligned.m8n8.x4.shared.b16 {%0,%1,%2,%3}, [%4];"
                 : "=r"(r[0]), "=r"(r[1]), "=r"(r[2]), "=r"(r[3]) : "r"(a));
}

// ---------------------------------------------------------------------------
// 128x128 tf32 GEMM, 1xTF32 (RNA-rounded operands), cp.async pipelined, BK=16.
// MODE 0: Cout = acc + bias (proj)
// MODE 1: scatter into g_Q (x0.125) / g_K / g_V^T, tf32-rounded (qkv)
// ---------------------------------------------------------------------------
#define ASTR 20
#define BSTR 136

template <int MODE>
__global__ __launch_bounds__(256) void mm1x(
    const float* __restrict__ A, const float* __restrict__ Bm,
    const float* __restrict__ bias, float* __restrict__ Cout,
    int K, int N)
{
    __shared__ float As[2][128][ASTR];
    __shared__ float Bs[2][16][BSTR];
    const int tid  = threadIdx.x;
    const int lane = tid & 31, warp = tid >> 5;
    const int g    = lane >> 2, tig = lane & 3;
    const int wm   = (warp >> 2) * 64, wn = (warp & 3) * 32;
    const int m0   = blockIdx.y * 128, n0 = blockIdx.x * 128;

    float acc[16][4];
#pragma unroll
    for (int t = 0; t < 16; t++)
#pragma unroll
        for (int r = 0; r < 4; r++) acc[t][r] = 0.f;

    const int T = K / 16;

    auto prefetch = [&](int s, int buf) {
#pragma unroll
        for (int j = 0; j < 2; j++) {
            int c = tid * 2 + j;
            int ar = c >> 2, ak = c & 3;
            cp16(&As[buf][ar][ak * 4], A + (size_t)(m0 + ar) * K + s * 16 + ak * 4);
            int bk = c >> 5, bn = c & 31;
            cp16(&Bs[buf][bk][bn * 4], Bm + (size_t)(s * 16 + bk) * N + n0 + bn * 4);
        }
    };

    prefetch(0, 0);
    CP_COMMIT();

    for (int t = 0; t < T; t++) {
        int nxt = (t + 1 < T) ? t + 1 : t;
        prefetch(nxt, (t + 1) & 1);
        CP_COMMIT();
        CP_WAIT1();
        __syncthreads();

        int buf = t & 1;
#pragma unroll
        for (int kk = 0; kk < 16; kk += 8) {
            unsigned af[4][4], bf[4][2];
#pragma unroll
            for (int i = 0; i < 4; i++) {
                int m = wm + 16 * i + g;
                af[i][0] = tf32_rna_u(As[buf][m][kk + tig]);
                af[i][1] = tf32_rna_u(As[buf][m + 8][kk + tig]);
                af[i][2] = tf32_rna_u(As[buf][m][kk + tig + 4]);
                af[i][3] = tf32_rna_u(As[buf][m + 8][kk + tig + 4]);
            }
#pragma unroll
            for (int j = 0; j < 4; j++) {
                int n = wn + 8 * j + g;
                bf[j][0] = tf32_rna_u(Bs[buf][kk + tig][n]);
                bf[j][1] = tf32_rna_u(Bs[buf][kk + tig + 4][n]);
            }
#pragma unroll
            for (int i = 0; i < 4; i++)
#pragma unroll
                for (int j = 0; j < 4; j++) mma8(acc[i * 4 + j], af[i], bf[j]);
        }
        __syncthreads();
    }

    if (MODE == 0) {
#pragma unroll
        for (int i = 0; i < 4; i++) {
#pragma unroll
            for (int j = 0; j < 4; j++) {
                int r0 = m0 + wm + 16 * i + g;
                int c0 = n0 + wn + 8 * j + 2 * tig;
                float b0 = bias[c0], b1 = bias[c0 + 1];
                float2 v0 = make_float2(acc[i * 4 + j][0] + b0, acc[i * 4 + j][1] + b1);
                float2 v1 = make_float2(acc[i * 4 + j][2] + b0, acc[i * 4 + j][3] + b1);
                *(float2*)(Cout + (size_t)r0 * N + c0) = v0;
                *(float2*)(Cout + (size_t)(r0 + 8) * N + c0) = v1;
            }
        }
    } else {
#pragma unroll
        for (int i = 0; i < 4; i++) {
#pragma unroll
            for (int j = 0; j < 4; j++) {
                int r0 = m0 + wm + 16 * i + g;
                int c0 = n0 + wn + 8 * j + 2 * tig;
                float b0 = bias[c0], b1 = bias[c0 + 1];
#pragma unroll
                for (int e = 0; e < 4; e++) {
                    int row = r0 + (e >> 1) * 8;
                    int col = c0 + (e & 1);
                    float v = acc[i * 4 + j][e] + ((e & 1) ? b1 : b0);
                    int three = col / C_;
                    int rem = col - three * C_;
                    int hh = rem >> 6, dd = rem & 63;
                    int bb = row >> 11, nn = row & (N_ - 1);
                    if (three == 0) {
                        size_t idx = (((size_t)(bb * H_ + hh) * N_) + nn) * D_ + dd;
                        g_Q[idx] = tf32_rna(v * 0.125f);
                    } else if (three == 1) {
                        size_t idx = (((size_t)(bb * H_ + hh) * N_) + nn) * D_ + dd;
                        g_K[idx] = tf32_rna(v);
                    } else {
                        // V transposed: [b,h,d,n]
                        size_t idx = (((size_t)(bb * H_ + hh) * D_) + dd) * N_ + nn;
                        g_V[idx] = tf32_rna(v);
                    }
                }
            }
        }
    }
}

// ---------------------------------------------------------------------------
// Flash attention, tf32 mma, single-buffer cp.async, ldmatrix fragment loads.
// Block = 64 queries x (b,h), 128 threads, 3 CTAs/SM (smem 57,344 B).
// Ks [key][d] stride 76; Vs [d][key] stride 76 (V transposed in gmem);
// P staged tf32-rounded, loaded via ldmatrix. All ldmatrix row walks are
// conflict-free at stride 76 (==12 mod 32).
// ---------------------------------------------------------------------------
#define ST_  76
#define STV_ 76

__global__ __launch_bounds__(128, 3) void flash_tf32(
    const float* __restrict__ alibi, const int* __restrict__ mask)
{
    extern __shared__ float sm[];
    float* Ks = sm;                         // [64 keys][ST_]
    float* Vs = sm + 64 * ST_;              // [64 d][STV_] (transposed V)
    float* PQ = Vs + 64 * STV_;             // [64][ST_]  (Q staging, then P)

    const int tid  = threadIdx.x;
    const int lane = tid & 31, w = tid >> 5;
    const int g    = lane >> 2, tig = lane & 3;
    const int q0   = blockIdx.x * 64, h = blockIdx.y, b = blockIdx.z;
    const int bh   = b * H_ + h;
    float* Ps = PQ + w * 16 * ST_;

    // ldmatrix per-lane address components (precomputed)
    const int lr  = lane & 7;          // row within 8-row matrix
    const int lc  = (lane >> 3) << 2;  // 0,4,8,12: float col offset of matrix
    const int pr  = ((lane >> 4) << 3) + lr;       // P: rows 0-7 / 8-15
    const int pc  = ((lane >> 3) & 1) << 2;        // P: col half 0 / 4

    // stage Q [64][64]
    const float* Qg = g_Q + ((size_t)bh * N_ + q0) * D_;
    for (int idx = tid; idx < 64 * 16; idx += 128) {
        int r = idx >> 4, c4 = (idx & 15) << 2;
        *(float4*)&PQ[r * ST_ + c4] = *(const float4*)(Qg + r * D_ + c4);
    }
    __syncthreads();

    // Q frags (resident)
    unsigned qf[8][4];
    {
        int rlo = w * 16 + g;
#pragma unroll
        for (int kf = 0; kf < 8; kf++) {
            qf[kf][0] = *(const unsigned*)&PQ[rlo * ST_ + 8 * kf + tig];
            qf[kf][1] = *(const unsigned*)&PQ[(rlo + 8) * ST_ + 8 * kf + tig];
            qf[kf][2] = *(const unsigned*)&PQ[rlo * ST_ + 8 * kf + tig + 4];
            qf[kf][3] = *(const unsigned*)&PQ[(rlo + 8) * ST_ + 8 * kf + tig + 4];
        }
    }

    float Oa[8][4];
#pragma unroll
    for (int nt = 0; nt < 8; nt++)
#pragma unroll
        for (int r = 0; r < 4; r++) Oa[nt][r] = 0.f;
    float mlo = -1e30f, mhi = -1e30f, llo = 0.f, lhi = 0.f;

    const float* Alo = alibi + ((size_t)bh * N_ + q0 + w * 16 + g) * N_;
    const float* Ahi = Alo + 8 * (size_t)N_;
    const int* Mb = mask + b * N_;

    const float* Kbase = g_K + (size_t)bh * N_ * D_;
    const float* Vbase = g_V + (size_t)bh * D_ * N_;   // transposed layout

    for (int kt = 0; kt < N_ / 64; kt++) {
        __syncthreads();   // prior tile's reads of Ks/Vs complete (and Q init)

        // fill K [key][d] and V^T [d][key] tiles
        {
            const float* Kt = Kbase + (size_t)kt * 64 * D_;
            const float* Vt = Vbase + kt * 64;
#pragma unroll
            for (int j = 0; j < 8; j++) {
                int c = tid * 8 + j;
                int row = c >> 4, kc = c & 15;
                cp16(&Ks[row * ST_ + kc * 4], Kt + row * D_ + kc * 4);
                cp16(&Vs[row * STV_ + kc * 4], Vt + (size_t)row * N_ + kc * 4);
            }
        }
        CP_COMMIT();
        CP_WAIT0();
        __syncthreads();

        // S = Q K^T (tile 16x64 per warp), K frags via ldmatrix.x4
        float Sa[8][4];
#pragma unroll
        for (int nt = 0; nt < 8; nt++)
#pragma unroll
            for (int r = 0; r < 4; r++) Sa[nt][r] = 0.f;
#pragma unroll
        for (int nt = 0; nt < 8; nt++) {
            unsigned kb[16];
#pragma unroll
            for (int k2 = 0; k2 < 4; k2++)
                ldsm4(kb + 4 * k2, &Ks[(8 * nt + lr) * ST_ + 16 * k2 + lc]);
#pragma unroll
            for (int kf = 0; kf < 8; kf++)
                mma8(Sa[nt], qf[kf], kb + (kf >> 1) * 4 + (kf & 1) * 2);
        }

        // + alibi + mask
        int kbase = kt * 64;
#pragma unroll
        for (int nt = 0; nt < 8; nt++) {
            int c = kbase + 8 * nt + 2 * tig;
            float2 alo = *(const float2*)(Alo + c);
            float2 ahi = *(const float2*)(Ahi + c);
            int2 mk = *(const int2*)(Mb + c);
            float m0v = mk.x ? -1e30f : 0.f;
            float m1v = mk.y ? -1e30f : 0.f;
            Sa[nt][0] += alo.x + m0v;
            Sa[nt][1] += alo.y + m1v;
            Sa[nt][2] += ahi.x + m0v;
            Sa[nt][3] += ahi.y + m1v;
        }

        // online softmax
        float mx0 = -1e38f, mx1 = -1e38f;
#pragma unroll
        for (int nt = 0; nt < 8; nt++) {
            mx0 = fmaxf(mx0, fmaxf(Sa[nt][0], Sa[nt][1]));
            mx1 = fmaxf(mx1, fmaxf(Sa[nt][2], Sa[nt][3]));
        }
        mx0 = fmaxf(mx0, __shfl_xor_sync(0xffffffffu, mx0, 1));
        mx0 = fmaxf(mx0, __shfl_xor_sync(0xffffffffu, mx0, 2));
        mx1 = fmaxf(mx1, __shfl_xor_sync(0xffffffffu, mx1, 1));
        mx1 = fmaxf(mx1, __shfl_xor_sync(0xffffffffu, mx1, 2));
        float mn0 = fmaxf(mlo, mx0), mn1 = fmaxf(mhi, mx1);
        float cr0 = __expf(mlo - mn0), cr1 = __expf(mhi - mn1);
        mlo = mn0; mhi = mn1;
        float rs0 = 0.f, rs1 = 0.f;
#pragma unroll
        for (int nt = 0; nt < 8; nt++) {
            float p0 = __expf(Sa[nt][0] - mn0);
            float p1 = __expf(Sa[nt][1] - mn0);
            float p2 = __expf(Sa[nt][2] - mn1);
            float p3 = __expf(Sa[nt][3] - mn1);
            Sa[nt][0] = p0; Sa[nt][1] = p1; Sa[nt][2] = p2; Sa[nt][3] = p3;
            rs0 += p0 + p1;
            rs1 += p2 + p3;
        }
        rs0 += __shfl_xor_sync(0xffffffffu, rs0, 1);
        rs0 += __shfl_xor_sync(0xffffffffu, rs0, 2);
        rs1 += __shfl_xor_sync(0xffffffffu, rs1, 1);
        rs1 += __shfl_xor_sync(0xffffffffu, rs1, 2);
        llo = llo * cr0 + rs0;
        lhi = lhi * cr1 + rs1;
#pragma unroll
        for (int nt = 0; nt < 8; nt++) {
            Oa[nt][0] *= cr0; Oa[nt][1] *= cr0;
            Oa[nt][2] *= cr1; Oa[nt][3] *= cr1;
        }

        // stage P (tf32-rounded BITS, warp-private rows)
#pragma unroll
        for (int nt = 0; nt < 8; nt++) {
            uint2 lo = make_uint2(tf32_rna_u(Sa[nt][0]), tf32_rna_u(Sa[nt][1]));
            uint2 hi = make_uint2(tf32_rna_u(Sa[nt][2]), tf32_rna_u(Sa[nt][3]));
            *(uint2*)&Ps[g * ST_ + 8 * nt + 2 * tig] = lo;
            *(uint2*)&Ps[(g + 8) * ST_ + 8 * nt + 2 * tig] = hi;
        }
        __syncwarp();

        // P frags via ldmatrix (1 x4 per kf; reorder r1<->r2 for A layout)
        unsigned pf[8][4];
#pragma unroll
        for (int kf = 0; kf < 8; kf++) {
            unsigned t4[4];
            ldsm4(t4, &Ps[pr * ST_ + 8 * kf + pc]);
            pf[kf][0] = t4[0]; pf[kf][1] = t4[2];
            pf[kf][2] = t4[1]; pf[kf][3] = t4[3];
        }

        // O += P V  (V frags via ldmatrix on transposed Vs)
#pragma unroll
        for (int nt = 0; nt < 8; nt++) {
            unsigned vb[16];
#pragma unroll
            for (int k2 = 0; k2 < 4; k2++)
                ldsm4(vb + 4 * k2, &Vs[(8 * nt + lr) * STV_ + 16 * k2 + lc]);
#pragma unroll
            for (int kf = 0; kf < 8; kf++)
                mma8(Oa[nt], pf[kf], vb + (kf >> 1) * 4 + (kf & 1) * 2);
        }
    }

    // normalize + write ctx [B*N, C], col = h*64 + d
    float i0 = 1.f / llo, i1 = 1.f / lhi;
    float* Cr  = g_ctx + (size_t)(b * N_ + q0 + w * 16 + g) * C_ + h * D_;
    float* Cr2 = Cr + 8 * (size_t)C_;
#pragma unroll
    for (int nt = 0; nt < 8; nt++) {
        int c = 8 * nt + 2 * tig;
        *(float2*)(Cr + c)  = make_float2(Oa[nt][0] * i0, Oa[nt][1] * i0);
        *(float2*)(Cr2 + c) = make_float2(Oa[nt][2] * i1, Oa[nt][3] * i1);
    }
}

// ---------------------------------------------------------------------------
extern "C" void kernel_launch(void* const* d_in, const int* in_sizes, int n_in,
                              void* d_out, int out_size)
{
    const float* x      = (const float*)d_in[0];
    const int*   mask   = (const int*)d_in[1];
    const float* alibi  = (const float*)d_in[2];
    const float* qkv_w  = (const float*)d_in[3];
    const float* qkv_b  = (const float*)d_in[4];
    const float* proj_w = (const float*)d_in[5];
    const float* proj_b = (const float*)d_in[6];
    float* out = (float*)d_out;

    void* ctx_ptr = nullptr;
    cudaGetSymbolAddress(&ctx_ptr, g_ctx);

    // 1) QKV projection (1xTF32, cp.async pipelined; V written transposed)
    mm1x<1><<<dim3((3 * C_) / 128, M_ / 128), 256>>>(
        x, qkv_w, qkv_b, nullptr, C_, 3 * C_);

    // 2) Flash attention (tf32 mma, ldmatrix fragments, 3 CTAs/SM)
    const int smem_bytes = (64 * ST_ + 64 * STV_ + 64 * ST_) * 4;   // 58368
    cudaFuncSetAttribute(flash_tf32, cudaFuncAttributeMaxDynamicSharedMemorySize,
                         smem_bytes);
    flash_tf32<<<dim3(N_ / 64, H_, B_), 128, smem_bytes>>>(alibi, mask);

    // 3) Output projection (1xTF32, cp.async pipelined)
    mm1x<0><<<dim3(C_ / 128, M_ / 128), 256>>>(
        (const float*)ctx_ptr, proj_w, proj_b, out, C_, C_);
}